// round 7
// baseline (speedup 1.0000x reference)
#include <cuda_runtime.h>
#include <math.h>

#define BB   64
#define TT   127
#define SEQ  128
#define ENC  2048
#define EMB  512
#define HID  512
#define VOC  10000
#define G4   2048      // 4*HID
#define EPSV 1e-5f

// ---------------- scratch (static device globals: allocation-free) ----------------
__device__ float g_seq [(size_t)BB * SEQ * EMB];          // LSTM input sequence
__device__ float g_xih [(size_t)BB * SEQ * G4];           // precomputed x@W_ih^T + bias
__device__ float g_out [(size_t)BB * SEQ * HID];          // LSTM hidden outputs (masked)
__device__ float g_attn[(size_t)BB * SEQ * HID];          // attention output
__device__ float g_hbuf[2][BB * HID];                     // ping-pong hidden state
__device__ float g_c   [BB * HID];                        // cell state

// ---------------- init h/c ----------------
__global__ void init_hc_kernel() {
    int i = blockIdx.x * blockDim.x + threadIdx.x;
    if (i < BB * HID) {
        g_hbuf[0][i] = 0.f;
        g_hbuf[1][i] = 0.f;
        g_c[i] = 0.f;
    }
}

// ---------------- fc1: feat[b,e] = x[b,:] . fc1_w[e,:] + fc1_b[e] -> g_seq[b,0,e] ----------------
__global__ void fc1_kernel(const float* __restrict__ x, const float* __restrict__ w,
                           const float* __restrict__ bias) {
    int idx = blockIdx.x * blockDim.x + threadIdx.x;   // 0..32767
    int b = idx >> 9;
    int e = idx & 511;
    const float4* xr = (const float4*)(x + (size_t)b * ENC);
    const float4* wr = (const float4*)(w + (size_t)e * ENC);
    float acc = 0.f;
#pragma unroll 8
    for (int k = 0; k < ENC / 4; k++) {
        float4 a = xr[k];
        float4 ww = wr[k];
        acc += a.x * ww.x + a.y * ww.y + a.z * ww.z + a.w * ww.w;
    }
    g_seq[(size_t)b * SEQ * EMB + e] = acc + bias[e];
}

// ---------------- BatchNorm1d (training: batch stats), in place on g_seq[:,0,:] ----------------
__global__ void bn_kernel(const float* __restrict__ gamma, const float* __restrict__ beta) {
    int e = blockIdx.x;        // 512 features
    int b = threadIdx.x;       // 64 batch
    __shared__ float red[64];
    float v = g_seq[(size_t)b * SEQ * EMB + e];
    red[b] = v;
    __syncthreads();
    for (int off = 32; off > 0; off >>= 1) {
        if (b < off) red[b] += red[b + off];
        __syncthreads();
    }
    float mu = red[0] * (1.f / BB);
    __syncthreads();
    float d = v - mu;
    red[b] = d * d;
    __syncthreads();
    for (int off = 32; off > 0; off >>= 1) {
        if (b < off) red[b] += red[b + off];
        __syncthreads();
    }
    float var = red[0] * (1.f / BB);
    g_seq[(size_t)b * SEQ * EMB + e] = d * rsqrtf(var + EPSV) * gamma[e] + beta[e];
}

// ---------------- embedding gather: g_seq[b, 1+t, :] = emb[y[b,t], :] ----------------
__global__ void embed_kernel(const int* __restrict__ y, const float* __restrict__ emb) {
    const int n4 = EMB / 4;                                   // 128
    int idx = blockIdx.x * blockDim.x + threadIdx.x;          // over B*T*n4 = 1,040,384 (exact)
    int d4 = idx % n4;
    int bt = idx / n4;
    int t = bt % TT;
    int b = bt / TT;
    int tok = y[b * TT + t];
    float4 v = ((const float4*)(emb + (size_t)tok * EMB))[d4];
    ((float4*)(g_seq + ((size_t)(b * SEQ + 1 + t)) * EMB))[d4] = v;
}

// ---------------- generic SIMT GEMM: C[M,N] = A[M,K] @ W[N,K]^T + b1 + b2 ----------------
#define GBM 128
#define GBN 128
#define GBK 16
__global__ void gemm_bias_kernel(const float* __restrict__ A, const float* __restrict__ W,
                                 const float* __restrict__ b1, const float* __restrict__ b2,
                                 float* __restrict__ C, int M, int N, int K) {
    __shared__ __align__(16) float As[GBK][GBM];
    __shared__ __align__(16) float Bs[GBK][GBN];
    int bm = blockIdx.y * GBM;
    int bn = blockIdx.x * GBN;
    int tid = threadIdx.x;                  // 256
    int tr = tid >> 4, tc = tid & 15;
    float acc[8][8];
#pragma unroll
    for (int i = 0; i < 8; i++)
#pragma unroll
        for (int j = 0; j < 8; j++) acc[i][j] = 0.f;

    for (int k0 = 0; k0 < K; k0 += GBK) {
#pragma unroll
        for (int i = 0; i < 2; i++) {
            int v = tid + i * 256;          // 0..511
            int m = v >> 2;                 // 0..127
            int kq = (v & 3) << 2;          // 0,4,8,12
            float4 a = make_float4(0.f, 0.f, 0.f, 0.f);
            if (bm + m < M) a = *(const float4*)(A + (size_t)(bm + m) * K + k0 + kq);
            As[kq + 0][m] = a.x; As[kq + 1][m] = a.y; As[kq + 2][m] = a.z; As[kq + 3][m] = a.w;
            float4 bb = make_float4(0.f, 0.f, 0.f, 0.f);
            if (bn + m < N) bb = *(const float4*)(W + (size_t)(bn + m) * K + k0 + kq);
            Bs[kq + 0][m] = bb.x; Bs[kq + 1][m] = bb.y; Bs[kq + 2][m] = bb.z; Bs[kq + 3][m] = bb.w;
        }
        __syncthreads();
#pragma unroll
        for (int k = 0; k < GBK; k++) {
            float4 a0 = *(const float4*)&As[k][tr * 8];
            float4 a1 = *(const float4*)&As[k][tr * 8 + 4];
            float4 c0 = *(const float4*)&Bs[k][tc * 8];
            float4 c1 = *(const float4*)&Bs[k][tc * 8 + 4];
            float ar[8] = {a0.x, a0.y, a0.z, a0.w, a1.x, a1.y, a1.z, a1.w};
            float br[8] = {c0.x, c0.y, c0.z, c0.w, c1.x, c1.y, c1.z, c1.w};
#pragma unroll
            for (int i = 0; i < 8; i++)
#pragma unroll
                for (int j = 0; j < 8; j++) acc[i][j] += ar[i] * br[j];
        }
        __syncthreads();
    }
#pragma unroll
    for (int i = 0; i < 8; i++) {
        int m = bm + tr * 8 + i;
        if (m >= M) continue;
#pragma unroll
        for (int j = 0; j < 8; j++) {
            int n = bn + tc * 8 + j;
            if (n >= N) continue;
            float bv = (b1 ? b1[n] : 0.f) + (b2 ? b2[n] : 0.f);
            C[(size_t)m * N + n] = acc[i][j] + bv;
        }
    }
}

// ---------------- one LSTM time step ----------------
// grid 128 blocks (4 hidden units each), 256 threads.
// thread (ul = tx>>6, b = tx&63) owns hidden unit u = u0+ul for batch b,
// accumulating all four gates -> pointwise update fully in registers.
// Warp lanes share the unit -> weight LDGs are warp-uniform (broadcast);
// h lives in smem with 129-float4 row pitch (conflict-free strided access).
__global__ void lstm_step_kernel(const float* __restrict__ whh,
                                 const int* __restrict__ lengths, int t) {
    extern __shared__ float4 sh4[];               // [64][129] float4 (padded rows)
    int tx = threadIdx.x;                         // 256
    int ul = tx >> 6;                             // 0..3
    int b  = tx & 63;                             // 0..63
    int u0 = blockIdx.x << 2;
    int src = t & 1;

    // stage old h (coalesced) into padded smem: ALL 64*128 = 8192 float4
    const float4* gh4 = (const float4*)g_hbuf[src];
#pragma unroll
    for (int i = 0; i < 32; i++) {
        int v = i * 256 + tx;                     // 0..8191
        int bb = v >> 7;                          // 0..63
        int kq = v & 127;
        sh4[bb * 129 + kq] = gh4[v];
    }
    __syncthreads();

    int u = u0 + ul;
    const float4* w0 = (const float4*)(whh + (size_t)(0 * HID + u) * HID);
    const float4* w1 = (const float4*)(whh + (size_t)(1 * HID + u) * HID);
    const float4* w2 = (const float4*)(whh + (size_t)(2 * HID + u) * HID);
    const float4* w3 = (const float4*)(whh + (size_t)(3 * HID + u) * HID);
    const float4* hrow = &sh4[b * 129];

    float acc0 = 0.f, acc1 = 0.f, acc2 = 0.f, acc3 = 0.f;
#pragma unroll 4
    for (int kq = 0; kq < 128; kq++) {
        float4 h4 = hrow[kq];
        float4 wa = w0[kq];
        acc0 += wa.x * h4.x + wa.y * h4.y + wa.z * h4.z + wa.w * h4.w;
        float4 wb = w1[kq];
        acc1 += wb.x * h4.x + wb.y * h4.y + wb.z * h4.z + wb.w * h4.w;
        float4 wc = w2[kq];
        acc2 += wc.x * h4.x + wc.y * h4.y + wc.z * h4.z + wc.w * h4.w;
        float4 wd = w3[kq];
        acc3 += wd.x * h4.x + wd.y * h4.y + wd.z * h4.z + wd.w * h4.w;
    }

    float* hdst = g_hbuf[src ^ 1];
    size_t base = (size_t)(b * SEQ + t) * G4;
    float gi = acc0 + g_xih[base + 0 * HID + u];
    float gf = acc1 + g_xih[base + 1 * HID + u];
    float gg = acc2 + g_xih[base + 2 * HID + u];
    float go = acc3 + g_xih[base + 3 * HID + u];
    float iv = 1.f / (1.f + expf(-gi));
    float fv = 1.f / (1.f + expf(-gf));
    float gv = tanhf(gg);
    float ov = 1.f / (1.f + expf(-go));
    float c = g_c[b * HID + u];
    c = fv * c + iv * gv;
    float h = ov * tanhf(c);
    g_c[b * HID + u] = c;
    hdst[b * HID + u] = h;
    g_out[(size_t)(b * SEQ + t) * HID + u] = (t < lengths[b]) ? h : 0.f;
}

// ---------------- masked self-attention ----------------
// block = (b, tile of 16 t), 256 threads
__global__ void attn_kernel() {
    __shared__ __align__(16) float4 sq4[16 * 128];   // 16 query rows (32KB)
    __shared__ __align__(16) float  ss[16 * 128];    // scores -> weights (8KB)
    int tx = threadIdx.x;
    int b = blockIdx.y;
    int t0 = blockIdx.x * 16;
    const float4* outb4 = (const float4*)(g_out + (size_t)b * SEQ * HID);

    for (int i = tx; i < 16 * 128; i += 256) {
        sq4[i] = outb4[t0 * 128 + i];
        ss[i] = 0.f;
    }
    __syncthreads();

    // scores: thread (tq, sg) does 8 s values
    int tq = tx >> 4, sg = tx & 15;
    int t = t0 + tq;
    for (int so = 0; so < 8; so++) {
        int s = sg * 8 + so;
        if (s < t) {
            const float4* kr = outb4 + s * 128;
            const float4* qr = sq4 + tq * 128;
            float d = 0.f;
#pragma unroll 8
            for (int kq = 0; kq < 128; kq++) {
                float4 a = qr[kq];
                float4 c = kr[kq];
                d += a.x * c.x + a.y * c.y + a.z * c.z + a.w * c.w;
            }
            ss[tq * 128 + s] = d;
        }
    }
    __syncthreads();

    // softmax over full 128-entry rows (masked entries are exact zeros, matching reference)
    if (tx < 128) {
        int row = tx >> 3, l8 = tx & 7;
        float m = -1e30f;
        for (int i = l8; i < 128; i += 8) m = fmaxf(m, ss[row * 128 + i]);
        for (int o = 4; o >= 1; o >>= 1) m = fmaxf(m, __shfl_xor_sync(0xffffffffu, m, o));
        float den = 0.f;
        for (int i = l8; i < 128; i += 8) den += __expf(ss[row * 128 + i] - m);
        for (int o = 4; o >= 1; o >>= 1) den += __shfl_xor_sync(0xffffffffu, den, o);
        float inv = 1.f / den;
        int trow = t0 + row;
        for (int i = l8; i < 128; i += 8) {
            float wv = (i < trow) ? __expf(ss[row * 128 + i] - m) * inv : 0.f;
            ss[row * 128 + i] = wv;
        }
    }
    __syncthreads();

    // weighted sum of value rows
    int d0 = tx << 1;
    float2 accv[16];
#pragma unroll
    for (int q = 0; q < 16; q++) { accv[q].x = 0.f; accv[q].y = 0.f; }
    for (int s = 0; s < SEQ; s++) {
        const float* orow = g_out + (size_t)(b * SEQ + s) * HID;
        float2 v = *(const float2*)(orow + d0);
#pragma unroll
        for (int q = 0; q < 16; q++) {
            float wv = ss[q * 128 + s];
            accv[q].x += wv * v.x;
            accv[q].y += wv * v.y;
        }
    }
#pragma unroll
    for (int q = 0; q < 16; q++) {
        float* arow = g_attn + (size_t)(b * SEQ + t0 + q) * HID;
        *(float2*)(arow + d0) = accv[q];
    }
}

// ---------------- host launch ----------------
extern "C" void kernel_launch(void* const* d_in, const int* in_sizes, int n_in,
                              void* d_out, int out_size) {
    (void)in_sizes; (void)n_in; (void)out_size;
    const float* x      = (const float*)d_in[0];
    const int*   y      = (const int*)  d_in[1];
    const int*   lens   = (const int*)  d_in[2];
    const float* fc1_w  = (const float*)d_in[3];
    const float* fc1_b  = (const float*)d_in[4];
    const float* bn_g   = (const float*)d_in[5];
    const float* bn_b   = (const float*)d_in[6];
    const float* emb    = (const float*)d_in[7];
    const float* w_ih   = (const float*)d_in[8];
    const float* w_hh   = (const float*)d_in[9];
    const float* b_ih   = (const float*)d_in[10];
    const float* b_hh   = (const float*)d_in[11];
    const float* fc2_w  = (const float*)d_in[12];
    const float* fc2_b  = (const float*)d_in[13];
    float* out = (float*)d_out;

    const int lstm_smem = 64 * 129 * 16;   // 132096 B
    cudaFuncSetAttribute(lstm_step_kernel, cudaFuncAttributeMaxDynamicSharedMemorySize, lstm_smem);

    float *p_seq, *p_xih, *p_attn;
    cudaGetSymbolAddress((void**)&p_seq,  g_seq);
    cudaGetSymbolAddress((void**)&p_xih,  g_xih);
    cudaGetSymbolAddress((void**)&p_attn, g_attn);

    init_hc_kernel<<<(BB * HID + 255) / 256, 256>>>();
    fc1_kernel<<<(BB * EMB) / 256, 256>>>(x, fc1_w, fc1_b);
    bn_kernel<<<EMB, 64>>>(bn_g, bn_b);
    embed_kernel<<<(BB * TT * (EMB / 4)) / 256, 256>>>(y, emb);

    // X_ih = seq @ W_ih^T + (b_ih + b_hh)
    {
        dim3 g(G4 / GBN, (BB * SEQ) / GBM);     // (16, 64)
        gemm_bias_kernel<<<g, 256>>>(p_seq, w_ih, b_ih, b_hh, p_xih, BB * SEQ, G4, EMB);
    }

    for (int t = 0; t < SEQ; t++)
        lstm_step_kernel<<<128, 256, lstm_smem>>>(w_hh, lens, t);

    attn_kernel<<<dim3(SEQ / 16, BB), 256>>>();

    // predictions = attn @ fc2_w^T + fc2_b
    {
        dim3 g((VOC + GBN - 1) / GBN, (BB * SEQ) / GBM);   // (79, 64)
        gemm_bias_kernel<<<g, 256>>>(p_attn, fc2_w, fc2_b, nullptr, out, BB * SEQ, VOC, HID);
    }
}

// round 11
// speedup vs baseline: 1.3153x; 1.3153x over previous
#include <cuda_runtime.h>
#include <cuda_bf16.h>
#include <math.h>
#include <stdint.h>

#define BB   64
#define TT   127
#define SEQ  128
#define ENC  2048
#define EMB  512
#define HID  512
#define VOC  10000
#define VOCP 10112     // VOC padded to 128-tile multiple (79*128)
#define G4   2048      // 4*HID
#define KDIM 512       // shared K for both big GEMMs
#define EPSV 1e-5f

// ---------------- scratch (static device globals: allocation-free) ----------------
__device__ float g_seq [(size_t)BB * SEQ * EMB];
__device__ float g_xih [(size_t)BB * SEQ * G4];
__device__ float g_out [(size_t)BB * SEQ * HID];
__device__ float g_attn[(size_t)BB * SEQ * HID];
__device__ float g_hbuf[2][BB * HID];
__device__ float g_c   [BB * HID];
// bf16 split buffers (hi + lo) for tensor-core GEMMs
__device__ __nv_bfloat16 g_Ah[(size_t)BB * SEQ * KDIM];
__device__ __nv_bfloat16 g_Al[(size_t)BB * SEQ * KDIM];
__device__ __nv_bfloat16 g_Wh[(size_t)VOCP * KDIM];
__device__ __nv_bfloat16 g_Wl[(size_t)VOCP * KDIM];

// ================= baseline-PTX tensor core helpers (portable, no 'a' features) =================
__device__ __forceinline__ uint32_t smem_u32(const void* p) {
    uint32_t a;
    asm("{ .reg .u64 t; cvta.to.shared.u64 t, %1; cvt.u32.u64 %0, t; }" : "=r"(a) : "l"(p));
    return a;
}
#define LDSM4(r, addr) \
    asm volatile("ldmatrix.sync.aligned.m8n8.x4.shared.b16 {%0,%1,%2,%3}, [%4];" \
                 : "=r"((r)[0]), "=r"((r)[1]), "=r"((r)[2]), "=r"((r)[3]) : "r"(addr))
#define MMA_BF16(c, a, b0v, b1v) \
    asm volatile("mma.sync.aligned.m16n8k16.row.col.f32.bf16.bf16.f32 " \
                 "{%0,%1,%2,%3}, {%4,%5,%6,%7}, {%8,%9}, {%0,%1,%2,%3};" \
                 : "+f"((c)[0]), "+f"((c)[1]), "+f"((c)[2]), "+f"((c)[3]) \
                 : "r"((a)[0]), "r"((a)[1]), "r"((a)[2]), "r"((a)[3]), "r"(b0v), "r"(b1v))

// ---------------- init h/c ----------------
__global__ void init_hc_kernel() {
    int i = blockIdx.x * blockDim.x + threadIdx.x;
    if (i < BB * HID) {
        g_hbuf[0][i] = 0.f;
        g_hbuf[1][i] = 0.f;
        g_c[i] = 0.f;
    }
}

// ---------------- fc1 ----------------
__global__ void fc1_kernel(const float* __restrict__ x, const float* __restrict__ w,
                           const float* __restrict__ bias) {
    int idx = blockIdx.x * blockDim.x + threadIdx.x;
    int b = idx >> 9;
    int e = idx & 511;
    const float4* xr = (const float4*)(x + (size_t)b * ENC);
    const float4* wr = (const float4*)(w + (size_t)e * ENC);
    float acc = 0.f;
#pragma unroll 8
    for (int k = 0; k < ENC / 4; k++) {
        float4 a = xr[k];
        float4 ww = wr[k];
        acc += a.x * ww.x + a.y * ww.y + a.z * ww.z + a.w * ww.w;
    }
    g_seq[(size_t)b * SEQ * EMB + e] = acc + bias[e];
}

// ---------------- BatchNorm1d (batch stats) ----------------
__global__ void bn_kernel(const float* __restrict__ gamma, const float* __restrict__ beta) {
    int e = blockIdx.x;
    int b = threadIdx.x;
    __shared__ float red[64];
    float v = g_seq[(size_t)b * SEQ * EMB + e];
    red[b] = v;
    __syncthreads();
    for (int off = 32; off > 0; off >>= 1) {
        if (b < off) red[b] += red[b + off];
        __syncthreads();
    }
    float mu = red[0] * (1.f / BB);
    __syncthreads();
    float d = v - mu;
    red[b] = d * d;
    __syncthreads();
    for (int off = 32; off > 0; off >>= 1) {
        if (b < off) red[b] += red[b + off];
        __syncthreads();
    }
    float var = red[0] * (1.f / BB);
    g_seq[(size_t)b * SEQ * EMB + e] = d * rsqrtf(var + EPSV) * gamma[e] + beta[e];
}

// ---------------- embedding gather ----------------
__global__ void embed_kernel(const int* __restrict__ y, const float* __restrict__ emb) {
    const int n4 = EMB / 4;
    int idx = blockIdx.x * blockDim.x + threadIdx.x;
    int d4 = idx % n4;
    int bt = idx / n4;
    int t = bt % TT;
    int b = bt / TT;
    int tok = y[b * TT + t];
    float4 v = ((const float4*)(emb + (size_t)tok * EMB))[d4];
    ((float4*)(g_seq + ((size_t)(b * SEQ + 1 + t)) * EMB))[d4] = v;
}

// ---------------- fp32 -> (bf16 hi, bf16 lo) split; pads rows >= rows_valid with zeros ----------------
__global__ void split_bf16_kernel(const float* __restrict__ src,
                                  __nv_bfloat16* __restrict__ dh, __nv_bfloat16* __restrict__ dl,
                                  int rows_valid, int rows_total) {
    long i = (long)blockIdx.x * blockDim.x + threadIdx.x;
    long e0 = i * 2;
    if (e0 >= (long)rows_total * KDIM) return;
    long r = e0 / KDIM;
    float2 v = (r < rows_valid) ? *(const float2*)(src + e0) : make_float2(0.f, 0.f);
    __nv_bfloat162 h, l;
    h.x = __float2bfloat16(v.x);
    h.y = __float2bfloat16(v.y);
    l.x = __float2bfloat16(v.x - __bfloat162float(h.x));
    l.y = __float2bfloat16(v.y - __bfloat162float(h.y));
    *(__nv_bfloat162*)(dh + e0) = h;
    *(__nv_bfloat162*)(dl + e0) = l;
}

// ---------------- warp-MMA split-bf16 GEMM: C[M,Nvalid] = A @ W^T + b1 (+ b2) ----------------
// Block tile 128x128, 8 warps (4 m x 2 n), warp tile 32x64, K chunks of 64 bf16.
// acc += Ah*Wh + Ah*Wl + Al*Wh  (fp32 accumulate; dropped lo*lo term ~2^-16)
#define PITCH 144   // bytes per 64-bf16 smem row (36 banks -> LDSM conflict-free)
#define T_AH 0
#define T_AL 18432
#define T_BH 36864
#define T_BL 55296
#define MMA_SMEM 73728
__global__ void mma_gemm_kernel(const __nv_bfloat16* __restrict__ Ah, const __nv_bfloat16* __restrict__ Al,
                                const __nv_bfloat16* __restrict__ Wh, const __nv_bfloat16* __restrict__ Wl,
                                const float* __restrict__ b1, const float* __restrict__ b2,
                                float* __restrict__ C, int Nvalid) {
    extern __shared__ char smem[];
    uint32_t sb = smem_u32(smem);
    int tid = threadIdx.x;                 // 256
    int lane = tid & 31, wid = tid >> 5;
    int wr = wid & 3, wc = wid >> 2;       // 4 x 2 warp grid
    int bm = blockIdx.y * 128, bn = blockIdx.x * 128;
    int m0 = wr * 32, n0 = wc * 64;

    float acc[2][8][4];
#pragma unroll
    for (int mi = 0; mi < 2; mi++)
#pragma unroll
        for (int nj = 0; nj < 8; nj++)
#pragma unroll
            for (int q = 0; q < 4; q++) acc[mi][nj][q] = 0.f;

    int grp = lane >> 3, l7 = lane & 7;
    // ldmatrix lane->row mapping (canonical m16n8k16 fragment order)
    uint32_t a_row  = (uint32_t)(((grp & 1) << 3) + l7);  // A: grp0 m0-7@k0, grp1 m8-15@k0, grp2 m0-7@k8, grp3 m8-15@k8
    uint32_t a_koff = (uint32_t)((grp >> 1) << 4);
    uint32_t b_row  = (uint32_t)(((grp >> 1) << 3) + l7); // B: grp0 n0-7@k0, grp1 n0-7@k8, grp2 n8-15@k0, grp3 n8-15@k8
    uint32_t b_koff = (uint32_t)((grp & 1) << 4);

    for (int c = 0; c < KDIM / 64; c++) {
        // stage 4 tiles of 128 rows x 64 bf16
#pragma unroll
        for (int it = 0; it < 4; it++) {
            int idx = it * 256 + tid;                 // 0..1023
            int r = idx >> 3, kq = idx & 7;
            uint32_t so = (uint32_t)(r * PITCH + kq * 16);
            size_t ga = (size_t)(bm + r) * KDIM + c * 64 + kq * 8;
            size_t gb = (size_t)(bn + r) * KDIM + c * 64 + kq * 8;
            *(uint4*)(smem + T_AH + so) = *(const uint4*)(Ah + ga);
            *(uint4*)(smem + T_AL + so) = *(const uint4*)(Al + ga);
            *(uint4*)(smem + T_BH + so) = *(const uint4*)(Wh + gb);
            *(uint4*)(smem + T_BL + so) = *(const uint4*)(Wl + gb);
        }
        __syncthreads();
#pragma unroll
        for (int ks = 0; ks < 4; ks++) {
            uint32_t kb = (uint32_t)(ks * 32);
            uint32_t aH[2][4], aL[2][4], bHf[4][4], bLf[4][4];
#pragma unroll
            for (int mi = 0; mi < 2; mi++) {
                uint32_t ad = sb + T_AH + (uint32_t)((m0 + mi * 16 + a_row) * PITCH) + kb + a_koff;
                LDSM4(aH[mi], ad);
                LDSM4(aL[mi], ad + (T_AL - T_AH));
            }
#pragma unroll
            for (int j = 0; j < 4; j++) {             // each x4 covers n-tiles 2j and 2j+1
                uint32_t bd = sb + T_BH + (uint32_t)((n0 + j * 16 + b_row) * PITCH) + kb + b_koff;
                LDSM4(bHf[j], bd);
                LDSM4(bLf[j], bd + (T_BL - T_BH));
            }
#pragma unroll
            for (int mi = 0; mi < 2; mi++)
#pragma unroll
                for (int nj = 0; nj < 8; nj++) {
                    int pr = nj >> 1, su = (nj & 1) << 1;
                    uint32_t bh0 = bHf[pr][su], bh1 = bHf[pr][su + 1];
                    uint32_t bl0 = bLf[pr][su], bl1 = bLf[pr][su + 1];
                    MMA_BF16(acc[mi][nj], aH[mi], bh0, bh1);
                    MMA_BF16(acc[mi][nj], aH[mi], bl0, bl1);
                    MMA_BF16(acc[mi][nj], aL[mi], bh0, bh1);
                }
        }
        __syncthreads();
    }

    // epilogue: c frag mapping: c0,c1 -> (row g, col 2i..), c2,c3 -> row g+8
    int gr = lane >> 2, gc = (lane & 3) * 2;
#pragma unroll
    for (int mi = 0; mi < 2; mi++) {
        int row = bm + m0 + mi * 16 + gr;
#pragma unroll
        for (int nj = 0; nj < 8; nj++) {
            int col = bn + n0 + nj * 8 + gc;
            if (col < Nvalid) {
                float bv0 = b1[col] + (b2 ? b2[col] : 0.f);
                float bv1 = b1[col + 1] + (b2 ? b2[col + 1] : 0.f);
                float2 v0 = make_float2(acc[mi][nj][0] + bv0, acc[mi][nj][1] + bv1);
                float2 v1 = make_float2(acc[mi][nj][2] + bv0, acc[mi][nj][3] + bv1);
                *(float2*)(C + (size_t)row * Nvalid + col) = v0;
                *(float2*)(C + (size_t)(row + 8) * Nvalid + col) = v1;
            }
        }
    }
}

// ---------------- one LSTM time step ----------------
__global__ void lstm_step_kernel(const float* __restrict__ whh,
                                 const int* __restrict__ lengths, int t) {
    extern __shared__ float4 sh4[];               // [64][129] float4 padded
    int tx = threadIdx.x;                         // 256
    int ul = tx >> 6;
    int b  = tx & 63;
    int u0 = blockIdx.x << 2;
    int src = t & 1;

    const float4* gh4 = (const float4*)g_hbuf[src];
#pragma unroll
    for (int i = 0; i < 32; i++) {
        int v = i * 256 + tx;
        int bb = v >> 7;
        int kq = v & 127;
        sh4[bb * 129 + kq] = gh4[v];
    }
    __syncthreads();

    int u = u0 + ul;
    const float4* w0 = (const float4*)(whh + (size_t)(0 * HID + u) * HID);
    const float4* w1 = (const float4*)(whh + (size_t)(1 * HID + u) * HID);
    const float4* w2 = (const float4*)(whh + (size_t)(2 * HID + u) * HID);
    const float4* w3 = (const float4*)(whh + (size_t)(3 * HID + u) * HID);
    const float4* hrow = &sh4[b * 129];

    float acc0 = 0.f, acc1 = 0.f, acc2 = 0.f, acc3 = 0.f;
#pragma unroll 4
    for (int kq = 0; kq < 128; kq++) {
        float4 h4 = hrow[kq];
        float4 wa = w0[kq];
        acc0 += wa.x * h4.x + wa.y * h4.y + wa.z * h4.z + wa.w * h4.w;
        float4 wb = w1[kq];
        acc1 += wb.x * h4.x + wb.y * h4.y + wb.z * h4.z + wb.w * h4.w;
        float4 wc = w2[kq];
        acc2 += wc.x * h4.x + wc.y * h4.y + wc.z * h4.z + wc.w * h4.w;
        float4 wd = w3[kq];
        acc3 += wd.x * h4.x + wd.y * h4.y + wd.z * h4.z + wd.w * h4.w;
    }

    float* hdst = g_hbuf[src ^ 1];
    size_t base = (size_t)(b * SEQ + t) * G4;
    float gi = acc0 + g_xih[base + 0 * HID + u];
    float gf = acc1 + g_xih[base + 1 * HID + u];
    float gg = acc2 + g_xih[base + 2 * HID + u];
    float go = acc3 + g_xih[base + 3 * HID + u];
    float iv = 1.f / (1.f + expf(-gi));
    float fv = 1.f / (1.f + expf(-gf));
    float gv = tanhf(gg);
    float ov = 1.f / (1.f + expf(-go));
    float c = g_c[b * HID + u];
    c = fv * c + iv * gv;
    float h = ov * tanhf(c);
    g_c[b * HID + u] = c;
    hdst[b * HID + u] = h;
    g_out[(size_t)(b * SEQ + t) * HID + u] = (t < lengths[b]) ? h : 0.f;
}

// ---------------- masked self-attention ----------------
__global__ void attn_kernel() {
    __shared__ __align__(16) float4 sq4[16 * 128];
    __shared__ __align__(16) float  ss[16 * 128];
    int tx = threadIdx.x;
    int b = blockIdx.y;
    int t0 = blockIdx.x * 16;
    const float4* outb4 = (const float4*)(g_out + (size_t)b * SEQ * HID);

    for (int i = tx; i < 16 * 128; i += 256) {
        sq4[i] = outb4[t0 * 128 + i];
        ss[i] = 0.f;
    }
    __syncthreads();

    int tq = tx >> 4, sg = tx & 15;
    int t = t0 + tq;
    for (int so = 0; so < 8; so++) {
        int s = sg * 8 + so;
        if (s < t) {
            const float4* kr = outb4 + s * 128;
            const float4* qr = sq4 + tq * 128;
            float d = 0.f;
#pragma unroll 8
            for (int kq = 0; kq < 128; kq++) {
                float4 a = qr[kq];
                float4 c = kr[kq];
                d += a.x * c.x + a.y * c.y + a.z * c.z + a.w * c.w;
            }
            ss[tq * 128 + s] = d;
        }
    }
    __syncthreads();

    if (tx < 128) {
        int row = tx >> 3, l8 = tx & 7;
        float m = -1e30f;
        for (int i = l8; i < 128; i += 8) m = fmaxf(m, ss[row * 128 + i]);
        for (int o = 4; o >= 1; o >>= 1) m = fmaxf(m, __shfl_xor_sync(0xffffffffu, m, o));
        float den = 0.f;
        for (int i = l8; i < 128; i += 8) den += __expf(ss[row * 128 + i] - m);
        for (int o = 4; o >= 1; o >>= 1) den += __shfl_xor_sync(0xffffffffu, den, o);
        float inv = 1.f / den;
        int trow = t0 + row;
        for (int i = l8; i < 128; i += 8) {
            float wv = (i < trow) ? __expf(ss[row * 128 + i] - m) * inv : 0.f;
            ss[row * 128 + i] = wv;
        }
    }
    __syncthreads();

    int d0 = tx << 1;
    float2 accv[16];
#pragma unroll
    for (int q = 0; q < 16; q++) { accv[q].x = 0.f; accv[q].y = 0.f; }
    for (int s = 0; s < SEQ; s++) {
        const float* orow = g_out + (size_t)(b * SEQ + s) * HID;
        float2 v = *(const float2*)(orow + d0);
#pragma unroll
        for (int q = 0; q < 16; q++) {
            float wv = ss[q * 128 + s];
            accv[q].x += wv * v.x;
            accv[q].y += wv * v.y;
        }
    }
#pragma unroll
    for (int q = 0; q < 16; q++) {
        float* arow = g_attn + (size_t)(b * SEQ + t0 + q) * HID;
        *(float2*)(arow + d0) = accv[q];
    }
}

// ---------------- host launch ----------------
extern "C" void kernel_launch(void* const* d_in, const int* in_sizes, int n_in,
                              void* d_out, int out_size) {
    (void)in_sizes; (void)n_in; (void)out_size;
    const float* x      = (const float*)d_in[0];
    const int*   y      = (const int*)  d_in[1];
    const int*   lens   = (const int*)  d_in[2];
    const float* fc1_w  = (const float*)d_in[3];
    const float* fc1_b  = (const float*)d_in[4];
    const float* bn_g   = (const float*)d_in[5];
    const float* bn_b   = (const float*)d_in[6];
    const float* emb    = (const float*)d_in[7];
    const float* w_ih   = (const float*)d_in[8];
    const float* w_hh   = (const float*)d_in[9];
    const float* b_ih   = (const float*)d_in[10];
    const float* b_hh   = (const float*)d_in[11];
    const float* fc2_w  = (const float*)d_in[12];
    const float* fc2_b  = (const float*)d_in[13];
    float* out = (float*)d_out;

    const int lstm_smem = 64 * 129 * 16;          // 132096 B
    cudaFuncSetAttribute(lstm_step_kernel, cudaFuncAttributeMaxDynamicSharedMemorySize, lstm_smem);
    cudaFuncSetAttribute(mma_gemm_kernel,  cudaFuncAttributeMaxDynamicSharedMemorySize, MMA_SMEM);

    float *p_seq, *p_xih, *p_attn;
    __nv_bfloat16 *p_Ah, *p_Al, *p_Wh, *p_Wl;
    cudaGetSymbolAddress((void**)&p_seq,  g_seq);
    cudaGetSymbolAddress((void**)&p_xih,  g_xih);
    cudaGetSymbolAddress((void**)&p_attn, g_attn);
    cudaGetSymbolAddress((void**)&p_Ah, g_Ah);
    cudaGetSymbolAddress((void**)&p_Al, g_Al);
    cudaGetSymbolAddress((void**)&p_Wh, g_Wh);
    cudaGetSymbolAddress((void**)&p_Wl, g_Wl);

    init_hc_kernel<<<(BB * HID + 255) / 256, 256>>>();
    fc1_kernel<<<(BB * EMB) / 256, 256>>>(x, fc1_w, fc1_b);
    bn_kernel<<<EMB, 64>>>(bn_g, bn_b);
    embed_kernel<<<(BB * TT * (EMB / 4)) / 256, 256>>>(y, emb);

    const int Mrows = BB * SEQ;                   // 8192

    // ---- X_ih = seq @ W_ih^T + (b_ih + b_hh) via split-bf16 warp MMA ----
    split_bf16_kernel<<<(Mrows * KDIM / 2 + 255) / 256, 256>>>(p_seq, p_Ah, p_Al, Mrows, Mrows);
    split_bf16_kernel<<<(G4 * KDIM / 2 + 255) / 256, 256>>>(w_ih, p_Wh, p_Wl, G4, G4);
    {
        dim3 g(G4 / 128, Mrows / 128);            // (16, 64)
        mma_gemm_kernel<<<g, 256, MMA_SMEM>>>(p_Ah, p_Al, p_Wh, p_Wl, b_ih, b_hh, p_xih, G4);
    }

    for (int t = 0; t < SEQ; t++)
        lstm_step_kernel<<<128, 256, lstm_smem>>>(w_hh, lens, t);

    attn_kernel<<<dim3(SEQ / 16, BB), 256>>>();

    // ---- predictions = attn @ fc2_w^T + fc2_b via split-bf16 warp MMA ----
    split_bf16_kernel<<<(Mrows * KDIM / 2 + 255) / 256, 256>>>(p_attn, p_Ah, p_Al, Mrows, Mrows);
    split_bf16_kernel<<<(VOCP * KDIM / 2 + 255) / 256, 256>>>(fc2_w, p_Wh, p_Wl, VOC, VOCP);
    {
        dim3 g(VOCP / 128, Mrows / 128);          // (79, 64)
        mma_gemm_kernel<<<g, 256, MMA_SMEM>>>(p_Ah, p_Al, p_Wh, p_Wl, fc2_b, nullptr, out, VOC);
    }
}

// round 12
// speedup vs baseline: 2.0040x; 1.5236x over previous
#include <cuda_runtime.h>
#include <cuda_bf16.h>
#include <math.h>
#include <stdint.h>

#define BB   64
#define TT   127
#define SEQ  128
#define ENC  2048
#define EMB  512
#define HID  512
#define VOC  10000
#define VOCP 10112     // VOC padded to 128-tile multiple (79*128)
#define G4   2048      // 4*HID
#define KDIM 512       // shared K for both big GEMMs
#define EPSV 1e-5f

// ---------------- scratch (static device globals: allocation-free) ----------------
__device__ float g_seq [(size_t)BB * SEQ * EMB];
__device__ float g_xih [(size_t)BB * SEQ * G4];
__device__ float g_out [(size_t)BB * SEQ * HID];
__device__ float g_attn[(size_t)BB * SEQ * HID];
__device__ float g_hbuf[2][BB * HID];
__device__ unsigned g_barrier;                            // grid barrier counter
// bf16 split buffers (hi + lo) for tensor-core GEMMs
__device__ __nv_bfloat16 g_Ah[(size_t)BB * SEQ * KDIM];
__device__ __nv_bfloat16 g_Al[(size_t)BB * SEQ * KDIM];
__device__ __nv_bfloat16 g_Wh[(size_t)VOCP * KDIM];
__device__ __nv_bfloat16 g_Wl[(size_t)VOCP * KDIM];

// ================= baseline-PTX helpers (portable, no 'a' features) =================
__device__ __forceinline__ uint32_t smem_u32(const void* p) {
    uint32_t a;
    asm("{ .reg .u64 t; cvta.to.shared.u64 t, %1; cvt.u32.u64 %0, t; }" : "=r"(a) : "l"(p));
    return a;
}
#define LDSM4(r, addr) \
    asm volatile("ldmatrix.sync.aligned.m8n8.x4.shared.b16 {%0,%1,%2,%3}, [%4];" \
                 : "=r"((r)[0]), "=r"((r)[1]), "=r"((r)[2]), "=r"((r)[3]) : "r"(addr))
#define MMA_BF16(c, a, b0v, b1v) \
    asm volatile("mma.sync.aligned.m16n8k16.row.col.f32.bf16.bf16.f32 " \
                 "{%0,%1,%2,%3}, {%4,%5,%6,%7}, {%8,%9}, {%0,%1,%2,%3};" \
                 : "+f"((c)[0]), "+f"((c)[1]), "+f"((c)[2]), "+f"((c)[3]) \
                 : "r"((a)[0]), "r"((a)[1]), "r"((a)[2]), "r"((a)[3]), "r"(b0v), "r"(b1v))
#define CPASYNC16(sa, gp) \
    asm volatile("cp.async.ca.shared.global [%0], [%1], 16;" :: "r"(sa), "l"(gp))
#define CP_COMMIT() asm volatile("cp.async.commit_group;" ::: "memory")

// ---------------- init h + barrier ----------------
__global__ void init_hc_kernel() {
    int i = blockIdx.x * blockDim.x + threadIdx.x;
    if (i == 0) g_barrier = 0u;
    if (i < BB * HID) {
        g_hbuf[0][i] = 0.f;
        g_hbuf[1][i] = 0.f;
    }
}

// ---------------- fc1 ----------------
__global__ void fc1_kernel(const float* __restrict__ x, const float* __restrict__ w,
                           const float* __restrict__ bias) {
    int idx = blockIdx.x * blockDim.x + threadIdx.x;
    int b = idx >> 9;
    int e = idx & 511;
    const float4* xr = (const float4*)(x + (size_t)b * ENC);
    const float4* wr = (const float4*)(w + (size_t)e * ENC);
    float acc = 0.f;
#pragma unroll 8
    for (int k = 0; k < ENC / 4; k++) {
        float4 a = xr[k];
        float4 ww = wr[k];
        acc += a.x * ww.x + a.y * ww.y + a.z * ww.z + a.w * ww.w;
    }
    g_seq[(size_t)b * SEQ * EMB + e] = acc + bias[e];
}

// ---------------- BatchNorm1d (batch stats) ----------------
__global__ void bn_kernel(const float* __restrict__ gamma, const float* __restrict__ beta) {
    int e = blockIdx.x;
    int b = threadIdx.x;
    __shared__ float red[64];
    float v = g_seq[(size_t)b * SEQ * EMB + e];
    red[b] = v;
    __syncthreads();
    for (int off = 32; off > 0; off >>= 1) {
        if (b < off) red[b] += red[b + off];
        __syncthreads();
    }
    float mu = red[0] * (1.f / BB);
    __syncthreads();
    float d = v - mu;
    red[b] = d * d;
    __syncthreads();
    for (int off = 32; off > 0; off >>= 1) {
        if (b < off) red[b] += red[b + off];
        __syncthreads();
    }
    float var = red[0] * (1.f / BB);
    g_seq[(size_t)b * SEQ * EMB + e] = d * rsqrtf(var + EPSV) * gamma[e] + beta[e];
}

// ---------------- embedding gather ----------------
__global__ void embed_kernel(const int* __restrict__ y, const float* __restrict__ emb) {
    const int n4 = EMB / 4;
    int idx = blockIdx.x * blockDim.x + threadIdx.x;
    int d4 = idx % n4;
    int bt = idx / n4;
    int t = bt % TT;
    int b = bt / TT;
    int tok = y[b * TT + t];
    float4 v = ((const float4*)(emb + (size_t)tok * EMB))[d4];
    ((float4*)(g_seq + ((size_t)(b * SEQ + 1 + t)) * EMB))[d4] = v;
}

// ---------------- fp32 -> (bf16 hi, bf16 lo) split; pads rows >= rows_valid with zeros ----------------
__global__ void split_bf16_kernel(const float* __restrict__ src,
                                  __nv_bfloat16* __restrict__ dh, __nv_bfloat16* __restrict__ dl,
                                  int rows_valid, int rows_total) {
    long i = (long)blockIdx.x * blockDim.x + threadIdx.x;
    long e0 = i * 2;
    if (e0 >= (long)rows_total * KDIM) return;
    long r = e0 / KDIM;
    float2 v = (r < rows_valid) ? *(const float2*)(src + e0) : make_float2(0.f, 0.f);
    __nv_bfloat162 h, l;
    h.x = __float2bfloat16(v.x);
    h.y = __float2bfloat16(v.y);
    l.x = __float2bfloat16(v.x - __bfloat162float(h.x));
    l.y = __float2bfloat16(v.y - __bfloat162float(h.y));
    *(__nv_bfloat162*)(dh + e0) = h;
    *(__nv_bfloat162*)(dl + e0) = l;
}

// ---------------- warp-MMA split-bf16 GEMM, 3-stage cp.async pipeline ----------------
// Block tile 128x128, 8 warps (4 m x 2 n), warp tile 32x64, K chunks of 64 bf16.
// acc += Ah*Wh + Ah*Wl + Al*Wh  (fp32 accumulate; dropped lo*lo term ~2^-16)
#define PITCH   144       // bytes per 64-bf16 smem row (36 banks -> LDSM conflict-free)
#define T_AH    0
#define T_AL    18432
#define T_BH    36864
#define T_BL    55296
#define STAGE_B 73728
#define NSTAGE  3
#define MMA_SMEM (STAGE_B * NSTAGE)   // 221184 B
#define NCHUNK  (KDIM / 64)           // 8

__global__ void __launch_bounds__(256, 1)
mma_gemm_kernel(const __nv_bfloat16* __restrict__ Ah, const __nv_bfloat16* __restrict__ Al,
                const __nv_bfloat16* __restrict__ Wh, const __nv_bfloat16* __restrict__ Wl,
                const float* __restrict__ b1, const float* __restrict__ b2,
                float* __restrict__ C, int Nvalid) {
    extern __shared__ char smem[];
    uint32_t sb = smem_u32(smem);
    int tid = threadIdx.x;                 // 256
    int lane = tid & 31, wid = tid >> 5;
    int wr = wid & 3, wc = wid >> 2;       // 4 x 2 warp grid
    int bm = blockIdx.y * 128, bn = blockIdx.x * 128;
    int m0 = wr * 32, n0 = wc * 64;

    // staging coords for this thread (4 rows x 1 16B-segment per tile per chunk-iter)
    int sr = tid >> 3, skq = tid & 7;      // covered via it-loop offsets of 32 rows

    float acc[2][8][4];
#pragma unroll
    for (int mi = 0; mi < 2; mi++)
#pragma unroll
        for (int nj = 0; nj < 8; nj++)
#pragma unroll
            for (int q = 0; q < 4; q++) acc[mi][nj][q] = 0.f;

    int grp = lane >> 3, l7 = lane & 7;
    uint32_t a_row  = (uint32_t)(((grp & 1) << 3) + l7);
    uint32_t a_koff = (uint32_t)((grp >> 1) << 4);
    uint32_t b_row  = (uint32_t)(((grp >> 1) << 3) + l7);
    uint32_t b_koff = (uint32_t)((grp & 1) << 4);

    // ---- stage chunk c into buffer buf via cp.async ----
    auto stage = [&](int c, int buf) {
        uint32_t base = sb + (uint32_t)(buf * STAGE_B);
#pragma unroll
        for (int it = 0; it < 4; it++) {
            int r = it * 32 + sr;
            uint32_t so = (uint32_t)(r * PITCH + skq * 16);
            size_t ga = (size_t)(bm + r) * KDIM + c * 64 + skq * 8;
            size_t gb = (size_t)(bn + r) * KDIM + c * 64 + skq * 8;
            CPASYNC16(base + T_AH + so, (const char*)(Ah + ga));
            CPASYNC16(base + T_AL + so, (const char*)(Al + ga));
            CPASYNC16(base + T_BH + so, (const char*)(Wh + gb));
            CPASYNC16(base + T_BL + so, (const char*)(Wl + gb));
        }
        CP_COMMIT();
    };

    stage(0, 0);
    stage(1, 1);

    for (int c = 0; c < NCHUNK; c++) {
        if (c + 2 < NCHUNK) stage(c + 2, (c + 2) % NSTAGE);
        if (c + 2 < NCHUNK)      asm volatile("cp.async.wait_group 2;" ::: "memory");
        else if (c + 1 < NCHUNK) asm volatile("cp.async.wait_group 1;" ::: "memory");
        else                     asm volatile("cp.async.wait_group 0;" ::: "memory");
        __syncthreads();

        uint32_t base = sb + (uint32_t)((c % NSTAGE) * STAGE_B);
#pragma unroll
        for (int ks = 0; ks < 4; ks++) {
            uint32_t kb = (uint32_t)(ks * 32);
            uint32_t aH[2][4], aL[2][4], bHf[4][4], bLf[4][4];
#pragma unroll
            for (int mi = 0; mi < 2; mi++) {
                uint32_t ad = base + T_AH + (uint32_t)((m0 + mi * 16 + a_row) * PITCH) + kb + a_koff;
                LDSM4(aH[mi], ad);
                LDSM4(aL[mi], ad + (T_AL - T_AH));
            }
#pragma unroll
            for (int j = 0; j < 4; j++) {
                uint32_t bd = base + T_BH + (uint32_t)((n0 + j * 16 + b_row) * PITCH) + kb + b_koff;
                LDSM4(bHf[j], bd);
                LDSM4(bLf[j], bd + (T_BL - T_BH));
            }
#pragma unroll
            for (int mi = 0; mi < 2; mi++)
#pragma unroll
                for (int nj = 0; nj < 8; nj++) {
                    int pr = nj >> 1, su = (nj & 1) << 1;
                    uint32_t bh0 = bHf[pr][su], bh1 = bHf[pr][su + 1];
                    uint32_t bl0 = bLf[pr][su], bl1 = bLf[pr][su + 1];
                    MMA_BF16(acc[mi][nj], aH[mi], bh0, bh1);
                    MMA_BF16(acc[mi][nj], aH[mi], bl0, bl1);
                    MMA_BF16(acc[mi][nj], aL[mi], bh0, bh1);
                }
        }
        __syncthreads();
    }

    int gr = lane >> 2, gc = (lane & 3) * 2;
#pragma unroll
    for (int mi = 0; mi < 2; mi++) {
        int row = bm + m0 + mi * 16 + gr;
#pragma unroll
        for (int nj = 0; nj < 8; nj++) {
            int col = bn + n0 + nj * 8 + gc;
            if (col < Nvalid) {
                float bv0 = b1[col] + (b2 ? b2[col] : 0.f);
                float bv1 = b1[col + 1] + (b2 ? b2[col + 1] : 0.f);
                float2 v0 = make_float2(acc[mi][nj][0] + bv0, acc[mi][nj][1] + bv1);
                float2 v1 = make_float2(acc[mi][nj][2] + bv0, acc[mi][nj][3] + bv1);
                *(float2*)(C + (size_t)row * Nvalid + col) = v0;
                *(float2*)(C + (size_t)(row + 8) * Nvalid + col) = v1;
            }
        }
    }
}

// ---------------- persistent LSTM: all 128 steps in one kernel ----------------
// grid 128 blocks (4 hidden units each), 256 threads; W_hh cached in smem once;
// cell state in registers; h exchanged via global (L2) + software grid barrier.
#define LSTM_H_SMEM (64 * 129 * 16)            // 132096 B (padded h buffer)
#define LSTM_W_SMEM (16 * 128 * 16)            // 32768 B  (16 gate-rows x 512 floats)
#define LSTM_SMEM   (LSTM_H_SMEM + LSTM_W_SMEM)
__global__ void __launch_bounds__(256, 1)
lstm_persist_kernel(const float* __restrict__ whh, const int* __restrict__ lengths,
                    const float* __restrict__ xih) {
    extern __shared__ float4 sdyn[];
    float4* sh4 = sdyn;                                   // [64][129]
    float4* sw4 = sdyn + (LSTM_H_SMEM / 16);              // [16][128]
    int tx = threadIdx.x;                                 // 256
    int ul = tx >> 6;                                     // 0..3
    int b  = tx & 63;                                     // 0..63
    int u0 = blockIdx.x << 2;
    int u  = u0 + ul;

    // cache this block's 16 W_hh rows (4 gates x 4 units), coalesced
    const float4* whh4 = (const float4*)whh;
    for (int i = tx; i < 16 * 128; i += 256) {
        int row = i >> 7, kq = i & 127;
        int g = row >> 2, l = row & 3;
        sw4[i] = whh4[(size_t)(g * HID + u0 + l) * (HID / 4) + kq];
    }

    const float4* wg0 = &sw4[(0 * 4 + ul) * 128];
    const float4* wg1 = &sw4[(1 * 4 + ul) * 128];
    const float4* wg2 = &sw4[(2 * 4 + ul) * 128];
    const float4* wg3 = &sw4[(3 * 4 + ul) * 128];

    float c = 0.f;
    int len = lengths[b];

    for (int t = 0; t < SEQ; t++) {
        int src = t & 1;
        // stage h(t-1) into padded smem; .cg to bypass L1 (ping-pong staleness)
        const float4* gh4 = (const float4*)g_hbuf[src];
#pragma unroll
        for (int i = 0; i < 32; i++) {
            int v = i * 256 + tx;
            sh4[(v >> 7) * 129 + (v & 127)] = __ldcg(&gh4[v]);
        }
        __syncthreads();

        const float4* hrow = &sh4[b * 129];
        float acc0 = 0.f, acc1 = 0.f, acc2 = 0.f, acc3 = 0.f;
#pragma unroll 4
        for (int kq = 0; kq < 128; kq++) {
            float4 h4 = hrow[kq];
            float4 wa = wg0[kq];
            acc0 += wa.x * h4.x + wa.y * h4.y + wa.z * h4.z + wa.w * h4.w;
            float4 wb = wg1[kq];
            acc1 += wb.x * h4.x + wb.y * h4.y + wb.z * h4.z + wb.w * h4.w;
            float4 wc = wg2[kq];
            acc2 += wc.x * h4.x + wc.y * h4.y + wc.z * h4.z + wc.w * h4.w;
            float4 wd = wg3[kq];
            acc3 += wd.x * h4.x + wd.y * h4.y + wd.z * h4.z + wd.w * h4.w;
        }

        size_t base = (size_t)(b * SEQ + t) * G4;
        float gi = acc0 + xih[base + 0 * HID + u];
        float gf = acc1 + xih[base + 1 * HID + u];
        float gg = acc2 + xih[base + 2 * HID + u];
        float go = acc3 + xih[base + 3 * HID + u];
        float iv = 1.f / (1.f + expf(-gi));
        float fv = 1.f / (1.f + expf(-gf));
        float gv = tanhf(gg);
        float ov = 1.f / (1.f + expf(-go));
        c = fv * c + iv * gv;
        float h = ov * tanhf(c);
        g_hbuf[src ^ 1][b * HID + u] = h;
        g_out[(size_t)(b * SEQ + t) * HID + u] = (t < len) ? h : 0.f;

        // grid barrier: publish h, arrive, spin, reconverge
        __threadfence();
        __syncthreads();
        if (tx == 0) {
            atomicAdd(&g_barrier, 1u);
            unsigned target = 128u * (unsigned)(t + 1);
            while (atomicAdd(&g_barrier, 0u) < target) { }
        }
        __syncthreads();
    }
}

// ---------------- masked self-attention ----------------
__global__ void attn_kernel() {
    __shared__ __align__(16) float4 sq4[16 * 128];
    __shared__ __align__(16) float  ss[16 * 128];
    int tx = threadIdx.x;
    int b = blockIdx.y;
    int t0 = blockIdx.x * 16;
    const float4* outb4 = (const float4*)(g_out + (size_t)b * SEQ * HID);

    for (int i = tx; i < 16 * 128; i += 256) {
        sq4[i] = outb4[t0 * 128 + i];
        ss[i] = 0.f;
    }
    __syncthreads();

    int tq = tx >> 4, sg = tx & 15;
    int t = t0 + tq;
    for (int so = 0; so < 8; so++) {
        int s = sg * 8 + so;
        if (s < t) {
            const float4* kr = outb4 + s * 128;
            const float4* qr = sq4 + tq * 128;
            float d = 0.f;
#pragma unroll 8
            for (int kq = 0; kq < 128; kq++) {
                float4 a = qr[kq];
                float4 c = kr[kq];
                d += a.x * c.x + a.y * c.y + a.z * c.z + a.w * c.w;
            }
            ss[tq * 128 + s] = d;
        }
    }
    __syncthreads();

    if (tx < 128) {
        int row = tx >> 3, l8 = tx & 7;
        float m = -1e30f;
        for (int i = l8; i < 128; i += 8) m = fmaxf(m, ss[row * 128 + i]);
        for (int o = 4; o >= 1; o >>= 1) m = fmaxf(m, __shfl_xor_sync(0xffffffffu, m, o));
        float den = 0.f;
        for (int i = l8; i < 128; i += 8) den += __expf(ss[row * 128 + i] - m);
        for (int o = 4; o >= 1; o >>= 1) den += __shfl_xor_sync(0xffffffffu, den, o);
        float inv = 1.f / den;
        int trow = t0 + row;
        for (int i = l8; i < 128; i += 8) {
            float wv = (i < trow) ? __expf(ss[row * 128 + i] - m) * inv : 0.f;
            ss[row * 128 + i] = wv;
        }
    }
    __syncthreads();

    int d0 = tx << 1;
    float2 accv[16];
#pragma unroll
    for (int q = 0; q < 16; q++) { accv[q].x = 0.f; accv[q].y = 0.f; }
    for (int s = 0; s < SEQ; s++) {
        const float* orow = g_out + (size_t)(b * SEQ + s) * HID;
        float2 v = *(const float2*)(orow + d0);
#pragma unroll
        for (int q = 0; q < 16; q++) {
            float wv = ss[q * 128 + s];
            accv[q].x += wv * v.x;
            accv[q].y += wv * v.y;
        }
    }
#pragma unroll
    for (int q = 0; q < 16; q++) {
        float* arow = g_attn + (size_t)(b * SEQ + t0 + q) * HID;
        *(float2*)(arow + d0) = accv[q];
    }
}

// ---------------- host launch ----------------
extern "C" void kernel_launch(void* const* d_in, const int* in_sizes, int n_in,
                              void* d_out, int out_size) {
    (void)in_sizes; (void)n_in; (void)out_size;
    const float* x      = (const float*)d_in[0];
    const int*   y      = (const int*)  d_in[1];
    const int*   lens   = (const int*)  d_in[2];
    const float* fc1_w  = (const float*)d_in[3];
    const float* fc1_b  = (const float*)d_in[4];
    const float* bn_g   = (const float*)d_in[5];
    const float* bn_b   = (const float*)d_in[6];
    const float* emb    = (const float*)d_in[7];
    const float* w_ih   = (const float*)d_in[8];
    const float* w_hh   = (const float*)d_in[9];
    const float* b_ih   = (const float*)d_in[10];
    const float* b_hh   = (const float*)d_in[11];
    const float* fc2_w  = (const float*)d_in[12];
    const float* fc2_b  = (const float*)d_in[13];
    float* out = (float*)d_out;

    cudaFuncSetAttribute(lstm_persist_kernel, cudaFuncAttributeMaxDynamicSharedMemorySize, LSTM_SMEM);
    cudaFuncSetAttribute(mma_gemm_kernel,     cudaFuncAttributeMaxDynamicSharedMemorySize, MMA_SMEM);

    float *p_seq, *p_xih, *p_attn;
    __nv_bfloat16 *p_Ah, *p_Al, *p_Wh, *p_Wl;
    cudaGetSymbolAddress((void**)&p_seq,  g_seq);
    cudaGetSymbolAddress((void**)&p_xih,  g_xih);
    cudaGetSymbolAddress((void**)&p_attn, g_attn);
    cudaGetSymbolAddress((void**)&p_Ah, g_Ah);
    cudaGetSymbolAddress((void**)&p_Al, g_Al);
    cudaGetSymbolAddress((void**)&p_Wh, g_Wh);
    cudaGetSymbolAddress((void**)&p_Wl, g_Wl);

    init_hc_kernel<<<(BB * HID + 255) / 256, 256>>>();
    fc1_kernel<<<(BB * EMB) / 256, 256>>>(x, fc1_w, fc1_b);
    bn_kernel<<<EMB, 64>>>(bn_g, bn_b);
    embed_kernel<<<(BB * TT * (EMB / 4)) / 256, 256>>>(y, emb);

    const int Mrows = BB * SEQ;                   // 8192

    // ---- X_ih = seq @ W_ih^T + (b_ih + b_hh) via split-bf16 warp MMA ----
    split_bf16_kernel<<<(Mrows * KDIM / 2 + 255) / 256, 256>>>(p_seq, p_Ah, p_Al, Mrows, Mrows);
    split_bf16_kernel<<<(G4 * KDIM / 2 + 255) / 256, 256>>>(w_ih, p_Wh, p_Wl, G4, G4);
    {
        dim3 g(G4 / 128, Mrows / 128);            // (16, 64)
        mma_gemm_kernel<<<g, 256, MMA_SMEM>>>(p_Ah, p_Al, p_Wh, p_Wl, b_ih, b_hh, p_xih, G4);
    }

    // ---- all 128 LSTM steps in ONE persistent kernel ----
    lstm_persist_kernel<<<128, 256, LSTM_SMEM>>>(w_hh, lens, p_xih);

    attn_kernel<<<dim3(SEQ / 16, BB), 256>>>();

    // ---- predictions = attn @ fc2_w^T + fc2_b via split-bf16 warp MMA ----
    split_bf16_kernel<<<(Mrows * KDIM / 2 + 255) / 256, 256>>>(p_attn, p_Ah, p_Al, Mrows, Mrows);
    split_bf16_kernel<<<(VOCP * KDIM / 2 + 255) / 256, 256>>>(fc2_w, p_Wh, p_Wl, VOC, VOCP);
    {
        dim3 g(VOCP / 128, Mrows / 128);          // (79, 64)
        mma_gemm_kernel<<<g, 256, MMA_SMEM>>>(p_Ah, p_Al, p_Wh, p_Wl, fc2_b, nullptr, out, VOC);
    }
}

// round 15
// speedup vs baseline: 2.1408x; 1.0682x over previous
#include <cuda_runtime.h>
#include <cuda_bf16.h>
#include <math.h>
#include <stdint.h>

#define BB   64
#define TT   127
#define SEQ  128
#define ENC  2048
#define EMB  512
#define HID  512
#define VOC  10000
#define VOCP 10240     // VOC padded to 256-tile multiple (40*256)
#define G4   2048      // 4*HID
#define KDIM 512       // shared K for both big GEMMs
#define EPSV 1e-5f

// ---------------- scratch (static device globals: allocation-free) ----------------
__device__ float g_seq [(size_t)BB * SEQ * EMB];
__device__ float g_xih [(size_t)BB * SEQ * G4];
__device__ float g_out [(size_t)BB * SEQ * HID];
__device__ float g_attn[(size_t)BB * SEQ * HID];
__device__ float g_hbuf[2][BB * HID];
__device__ unsigned g_barrier;                            // grid barrier counter
// bf16 split buffers (hi + lo) for tensor-core GEMMs
__device__ __nv_bfloat16 g_Ah[(size_t)BB * SEQ * KDIM];
__device__ __nv_bfloat16 g_Al[(size_t)BB * SEQ * KDIM];
__device__ __nv_bfloat16 g_Wh[(size_t)VOCP * KDIM];
__device__ __nv_bfloat16 g_Wl[(size_t)VOCP * KDIM];

// ================= baseline-PTX helpers (portable, no 'a' features) =================
__device__ __forceinline__ uint32_t smem_u32(const void* p) {
    uint32_t a;
    asm("{ .reg .u64 t; cvta.to.shared.u64 t, %1; cvt.u32.u64 %0, t; }" : "=r"(a) : "l"(p));
    return a;
}
#define LDSM4(r, addr) \
    asm volatile("ldmatrix.sync.aligned.m8n8.x4.shared.b16 {%0,%1,%2,%3}, [%4];" \
                 : "=r"((r)[0]), "=r"((r)[1]), "=r"((r)[2]), "=r"((r)[3]) : "r"(addr))
#define MMA_BF16(c, a, b0v, b1v) \
    asm volatile("mma.sync.aligned.m16n8k16.row.col.f32.bf16.bf16.f32 " \
                 "{%0,%1,%2,%3}, {%4,%5,%6,%7}, {%8,%9}, {%0,%1,%2,%3};" \
                 : "+f"((c)[0]), "+f"((c)[1]), "+f"((c)[2]), "+f"((c)[3]) \
                 : "r"((a)[0]), "r"((a)[1]), "r"((a)[2]), "r"((a)[3]), "r"(b0v), "r"(b1v))
#define CPASYNC16(sa, gp) \
    asm volatile("cp.async.ca.shared.global [%0], [%1], 16;" :: "r"(sa), "l"(gp))
#define CP_COMMIT() asm volatile("cp.async.commit_group;" ::: "memory")
// packed dual-fp32 FMA (PTX ISA 8.6, sm_100 family-common): acc += a * b, lanewise
#define FMA2(acc, a, b) \
    asm("fma.rn.f32x2 %0, %1, %2, %0;" : "+l"(acc) : "l"(a), "l"(b))

// ---------------- init h + barrier ----------------
__global__ void init_hc_kernel() {
    int i = blockIdx.x * blockDim.x + threadIdx.x;
    if (i == 0) g_barrier = 0u;
    if (i < BB * HID) {
        g_hbuf[0][i] = 0.f;
        g_hbuf[1][i] = 0.f;
    }
}

// ---------------- fc1 ----------------
__global__ void fc1_kernel(const float* __restrict__ x, const float* __restrict__ w,
                           const float* __restrict__ bias) {
    int idx = blockIdx.x * blockDim.x + threadIdx.x;
    int b = idx >> 9;
    int e = idx & 511;
    const float4* xr = (const float4*)(x + (size_t)b * ENC);
    const float4* wr = (const float4*)(w + (size_t)e * ENC);
    float acc = 0.f;
#pragma unroll 8
    for (int k = 0; k < ENC / 4; k++) {
        float4 a = xr[k];
        float4 ww = wr[k];
        acc += a.x * ww.x + a.y * ww.y + a.z * ww.z + a.w * ww.w;
    }
    g_seq[(size_t)b * SEQ * EMB + e] = acc + bias[e];
}

// ---------------- BatchNorm1d (batch stats) ----------------
__global__ void bn_kernel(const float* __restrict__ gamma, const float* __restrict__ beta) {
    int e = blockIdx.x;
    int b = threadIdx.x;
    __shared__ float red[64];
    float v = g_seq[(size_t)b * SEQ * EMB + e];
    red[b] = v;
    __syncthreads();
    for (int off = 32; off > 0; off >>= 1) {
        if (b < off) red[b] += red[b + off];
        __syncthreads();
    }
    float mu = red[0] * (1.f / BB);
    __syncthreads();
    float d = v - mu;
    red[b] = d * d;
    __syncthreads();
    for (int off = 32; off > 0; off >>= 1) {
        if (b < off) red[b] += red[b + off];
        __syncthreads();
    }
    float var = red[0] * (1.f / BB);
    g_seq[(size_t)b * SEQ * EMB + e] = d * rsqrtf(var + EPSV) * gamma[e] + beta[e];
}

// ---------------- embedding gather ----------------
__global__ void embed_kernel(const int* __restrict__ y, const float* __restrict__ emb) {
    const int n4 = EMB / 4;
    int idx = blockIdx.x * blockDim.x + threadIdx.x;
    int d4 = idx % n4;
    int bt = idx / n4;
    int t = bt % TT;
    int b = bt / TT;
    int tok = y[b * TT + t];
    float4 v = ((const float4*)(emb + (size_t)tok * EMB))[d4];
    ((float4*)(g_seq + ((size_t)(b * SEQ + 1 + t)) * EMB))[d4] = v;
}

// ---------------- fp32 -> (bf16 hi, bf16 lo) split; pads rows >= rows_valid with zeros ----------------
__global__ void split_bf16_kernel(const float* __restrict__ src,
                                  __nv_bfloat16* __restrict__ dh, __nv_bfloat16* __restrict__ dl,
                                  int rows_valid, int rows_total) {
    long i = (long)blockIdx.x * blockDim.x + threadIdx.x;
    long e0 = i * 2;
    if (e0 >= (long)rows_total * KDIM) return;
    long r = e0 / KDIM;
    float2 v = (r < rows_valid) ? *(const float2*)(src + e0) : make_float2(0.f, 0.f);
    __nv_bfloat162 h, l;
    h.x = __float2bfloat16(v.x);
    h.y = __float2bfloat16(v.y);
    l.x = __float2bfloat16(v.x - __bfloat162float(h.x));
    l.y = __float2bfloat16(v.y - __bfloat162float(h.y));
    *(__nv_bfloat162*)(dh + e0) = h;
    *(__nv_bfloat162*)(dl + e0) = l;
}

// ---------------- warp-MMA split-bf16 GEMM, 2-stage cp.async pipeline ----------------
// Block tile 128x256, 8 warps (2 m x 4 n), warp tile 64x64, K chunks of 64 bf16.
// acc += Ah*Wh + Ah*Wl + Al*Wh  (fp32 accumulate; dropped lo*lo term ~2^-16)
#define PITCH   144       // bytes per 64-bf16 smem row (36 banks -> LDSM conflict-free)
#define T_AH    0
#define T_AL    18432     // 128*144
#define T_BH    36864
#define T_BL    73728     // T_BH + 256*144
#define STAGE_B 110592    // T_BL + 256*144
#define NSTAGE  2
#define MMA_SMEM (STAGE_B * NSTAGE)   // 221184 B
#define NCHUNK  (KDIM / 64)           // 8

__global__ void __launch_bounds__(256, 1)
mma_gemm_kernel(const __nv_bfloat16* __restrict__ Ah, const __nv_bfloat16* __restrict__ Al,
                const __nv_bfloat16* __restrict__ Wh, const __nv_bfloat16* __restrict__ Wl,
                const float* __restrict__ b1, const float* __restrict__ b2,
                float* __restrict__ C, int Nvalid) {
    extern __shared__ char smem[];
    uint32_t sb = smem_u32(smem);
    int tid = threadIdx.x;                 // 256
    int lane = tid & 31, wid = tid >> 5;
    int wr = wid & 1, wc = wid >> 1;       // 2 m x 4 n warp grid
    int bm = blockIdx.y * 128, bn = blockIdx.x * 256;
    int m0 = wr * 64, n0 = wc * 64;

    int sr8 = tid >> 3, skq = tid & 7;     // staging decomposition

    float acc[4][8][4];
#pragma unroll
    for (int mi = 0; mi < 4; mi++)
#pragma unroll
        for (int nj = 0; nj < 8; nj++)
#pragma unroll
            for (int q = 0; q < 4; q++) acc[mi][nj][q] = 0.f;

    int grp = lane >> 3, l7 = lane & 7;
    uint32_t a_row  = (uint32_t)(((grp & 1) << 3) + l7);
    uint32_t a_koff = (uint32_t)((grp >> 1) << 4);
    uint32_t b_row  = (uint32_t)(((grp >> 1) << 3) + l7);
    uint32_t b_koff = (uint32_t)((grp & 1) << 4);

    // ---- stage chunk c into buffer buf via cp.async (6144 x 16B segments) ----
    auto stage = [&](int c, int buf) {
        uint32_t base = sb + (uint32_t)(buf * STAGE_B);
        int kcol = c * 64 + skq * 8;
#pragma unroll
        for (int it = 0; it < 24; it++) {
            int idx = it * 256 + tid;
            if (idx < 1024) {                 // AH: r = idx>>3 (0..127)
                int r = idx >> 3;
                uint32_t so = (uint32_t)(r * PITCH + skq * 16);
                CPASYNC16(base + T_AH + so, (const char*)(Ah + (size_t)(bm + r) * KDIM + kcol));
            } else if (idx < 2048) {          // AL
                int r = (idx - 1024) >> 3;
                uint32_t so = (uint32_t)(r * PITCH + skq * 16);
                CPASYNC16(base + T_AL + so, (const char*)(Al + (size_t)(bm + r) * KDIM + kcol));
            } else if (idx < 4096) {          // BH: r = 0..255
                int r = (idx - 2048) >> 3;
                uint32_t so = (uint32_t)(r * PITCH + skq * 16);
                CPASYNC16(base + T_BH + so, (const char*)(Wh + (size_t)(bn + r) * KDIM + kcol));
            } else {                          // BL
                int r = (idx - 4096) >> 3;
                uint32_t so = (uint32_t)(r * PITCH + skq * 16);
                CPASYNC16(base + T_BL + so, (const char*)(Wl + (size_t)(bn + r) * KDIM + kcol));
            }
        }
        CP_COMMIT();
    };

    stage(0, 0);
    stage(1, 1);

    for (int c = 0; c < NCHUNK; c++) {
        if (c + 1 < NCHUNK) asm volatile("cp.async.wait_group 1;" ::: "memory");
        else                asm volatile("cp.async.wait_group 0;" ::: "memory");
        __syncthreads();

        uint32_t base = sb + (uint32_t)((c & 1) * STAGE_B);
#pragma unroll
        for (int ks = 0; ks < 4; ks++) {
            uint32_t kb = (uint32_t)(ks * 32);
            uint32_t aH[4][4], aL[4][4], bHf[4][4], bLf[4][4];
#pragma unroll
            for (int mi = 0; mi < 4; mi++) {
                uint32_t ad = base + T_AH + (uint32_t)((m0 + mi * 16 + a_row) * PITCH) + kb + a_koff;
                LDSM4(aH[mi], ad);
                LDSM4(aL[mi], ad + (T_AL - T_AH));
            }
#pragma unroll
            for (int j = 0; j < 4; j++) {
                uint32_t bd = base + T_BH + (uint32_t)((n0 + j * 16 + b_row) * PITCH) + kb + b_koff;
                LDSM4(bHf[j], bd);
                LDSM4(bLf[j], bd + (T_BL - T_BH));
            }
#pragma unroll
            for (int mi = 0; mi < 4; mi++)
#pragma unroll
                for (int nj = 0; nj < 8; nj++) {
                    int pr = nj >> 1, su = (nj & 1) << 1;
                    uint32_t bh0 = bHf[pr][su], bh1 = bHf[pr][su + 1];
                    uint32_t bl0 = bLf[pr][su], bl1 = bLf[pr][su + 1];
                    MMA_BF16(acc[mi][nj], aH[mi], bh0, bh1);
                    MMA_BF16(acc[mi][nj], aH[mi], bl0, bl1);
                    MMA_BF16(acc[mi][nj], aL[mi], bh0, bh1);
                }
        }
        __syncthreads();
        if (c + 2 < NCHUNK) stage(c + 2, c & 1);
    }

    int gr = lane >> 2, gc = (lane & 3) * 2;
#pragma unroll
    for (int mi = 0; mi < 4; mi++) {
        int row = bm + m0 + mi * 16 + gr;
#pragma unroll
        for (int nj = 0; nj < 8; nj++) {
            int col = bn + n0 + nj * 8 + gc;
            if (col < Nvalid) {
                float bv0 = b1[col] + (b2 ? b2[col] : 0.f);
                float bv1 = b1[col + 1] + (b2 ? b2[col + 1] : 0.f);
                float2 v0 = make_float2(acc[mi][nj][0] + bv0, acc[mi][nj][1] + bv1);
                float2 v1 = make_float2(acc[mi][nj][2] + bv0, acc[mi][nj][3] + bv1);
                *(float2*)(C + (size_t)row * Nvalid + col) = v0;
                *(float2*)(C + (size_t)(row + 8) * Nvalid + col) = v1;
            }
        }
    }
}

// ---------------- persistent LSTM: all 128 steps in one kernel ----------------
// grid 128 blocks (4 hidden units each), 256 threads; W_hh cached in smem once;
// cell state in registers; h exchanged via global (L2) + software grid barrier.
// Inner product uses packed fma.rn.f32x2 (2 MACs/instr) with 8 independent accumulators.
#define LSTM_H_SMEM (64 * 129 * 16)            // 132096 B (padded h buffer)
#define LSTM_W_SMEM (16 * 128 * 16)            // 32768 B  (16 gate-rows x 512 floats)
#define LSTM_SMEM   (LSTM_H_SMEM + LSTM_W_SMEM)
__global__ void __launch_bounds__(256, 1)
lstm_persist_kernel(const float* __restrict__ whh, const int* __restrict__ lengths,
                    const float* __restrict__ xih) {
    extern __shared__ float4 sdyn[];
    float4* sh4 = sdyn;                                   // [64][129]
    float4* sw4 = sdyn + (LSTM_H_SMEM / 16);              // [16][128]
    int tx = threadIdx.x;                                 // 256
    int ul = tx >> 6;                                     // 0..3
    int b  = tx & 63;                                     // 0..63
    int u0 = blockIdx.x << 2;
    int u  = u0 + ul;

    // cache this block's 16 W_hh rows (4 gates x 4 units), coalesced
    const float4* whh4 = (const float4*)whh;
    for (int i = tx; i < 16 * 128; i += 256) {
        int row = i >> 7, kq = i & 127;
        int g = row >> 2, l = row & 3;
        sw4[i] = whh4[(size_t)(g * HID + u0 + l) * (HID / 4) + kq];
    }

    const double2* wg0 = (const double2*)&sw4[(0 * 4 + ul) * 128];
    const double2* wg1 = (const double2*)&sw4[(1 * 4 + ul) * 128];
    const double2* wg2 = (const double2*)&sw4[(2 * 4 + ul) * 128];
    const double2* wg3 = (const double2*)&sw4[(3 * 4 + ul) * 128];

    float c = 0.f;
    int len = lengths[b];

    for (int t = 0; t < SEQ; t++) {
        int src = t & 1;
        // stage h(t-1) into padded smem; .cg to bypass L1 (ping-pong staleness)
        const float4* gh4 = (const float4*)g_hbuf[src];
#pragma unroll
        for (int i = 0; i < 32; i++) {
            int v = i * 256 + tx;
            sh4[(v >> 7) * 129 + (v & 127)] = __ldcg(&gh4[v]);
        }
        __syncthreads();

        const double2* hrow = (const double2*)&sh4[b * 129];
        // 8 independent packed accumulators (4 gates x {xy, zw})
        unsigned long long a0x = 0ull, a0z = 0ull, a1x = 0ull, a1z = 0ull;
        unsigned long long a2x = 0ull, a2z = 0ull, a3x = 0ull, a3z = 0ull;
#pragma unroll 4
        for (int kq = 0; kq < 128; kq++) {
            double2 h2 = hrow[kq];
            unsigned long long hx = __double_as_longlong(h2.x);
            unsigned long long hz = __double_as_longlong(h2.y);
            double2 w;
            w = wg0[kq];
            FMA2(a0x, __double_as_longlong(w.x), hx);
            FMA2(a0z, __double_as_longlong(w.y), hz);
            w = wg1[kq];
            FMA2(a1x, __double_as_longlong(w.x), hx);
            FMA2(a1z, __double_as_longlong(w.y), hz);
            w = wg2[kq];
            FMA2(a2x, __double_as_longlong(w.x), hx);
            FMA2(a2z, __double_as_longlong(w.y), hz);
            w = wg3[kq];
            FMA2(a3x, __double_as_longlong(w.x), hx);
            FMA2(a3z, __double_as_longlong(w.y), hz);
        }
#define HSUM(a, b) (__uint_as_float((unsigned)((a) & 0xffffffffu)) + __uint_as_float((unsigned)((a) >> 32)) + \
                    __uint_as_float((unsigned)((b) & 0xffffffffu)) + __uint_as_float((unsigned)((b) >> 32)))
        float acc0 = HSUM(a0x, a0z);
        float acc1 = HSUM(a1x, a1z);
        float acc2 = HSUM(a2x, a2z);
        float acc3 = HSUM(a3x, a3z);
#undef HSUM

        size_t base = (size_t)(b * SEQ + t) * G4;
        float gi = acc0 + xih[base + 0 * HID + u];
        float gf = acc1 + xih[base + 1 * HID + u];
        float gg = acc2 + xih[base + 2 * HID + u];
        float go = acc3 + xih[base + 3 * HID + u];
        float iv = 1.f / (1.f + expf(-gi));
        float fv = 1.f / (1.f + expf(-gf));
        float gv = tanhf(gg);
        float ov = 1.f / (1.f + expf(-go));
        c = fv * c + iv * gv;
        float h = ov * tanhf(c);
        g_hbuf[src ^ 1][b * HID + u] = h;
        g_out[(size_t)(b * SEQ + t) * HID + u] = (t < len) ? h : 0.f;

        // grid barrier: publish h, arrive, spin, reconverge
        __threadfence();
        __syncthreads();
        if (tx == 0) {
            atomicAdd(&g_barrier, 1u);
            unsigned target = 128u * (unsigned)(t + 1);
            while (atomicAdd(&g_barrier, 0u) < target) { }
        }
        __syncthreads();
    }
}

// ---------------- masked self-attention ----------------
__global__ void attn_kernel() {
    __shared__ __align__(16) float4 sq4[16 * 128];
    __shared__ __align__(16) float  ss[16 * 128];
    int tx = threadIdx.x;
    int b = blockIdx.y;
    int t0 = blockIdx.x * 16;
    const float4* outb4 = (const float4*)(g_out + (size_t)b * SEQ * HID);

    for (int i = tx; i < 16 * 128; i += 256) {
        sq4[i] = outb4[t0 * 128 + i];
        ss[i] = 0.f;
    }
    __syncthreads();

    int tq = tx >> 4, sg = tx & 15;
    int t = t0 + tq;
    for (int so = 0; so < 8; so++) {
        int s = sg * 8 + so;
        if (s < t) {
            const float4* kr = outb4 + s * 128;
            const float4* qr = sq4 + tq * 128;
            float d = 0.f;
#pragma unroll 8
            for (int kq = 0; kq < 128; kq++) {
                float4 a = qr[kq];
                float4 c = kr[kq];
                d += a.x * c.x + a.y * c.y + a.z * c.z + a.w * c.w;
            }
            ss[tq * 128 + s] = d;
        }
    }
    __syncthreads();

    if (tx < 128) {
        int row = tx >> 3, l8 = tx & 7;
        float m = -1e30f;
        for (int i = l8; i < 128; i += 8) m = fmaxf(m, ss[row * 128 + i]);
        for (int o = 4; o >= 1; o >>= 1) m = fmaxf(m, __shfl_xor_sync(0xffffffffu, m, o));
        float den = 0.f;
        for (int i = l8; i < 128; i += 8) den += __expf(ss[row * 128 + i] - m);
        for (int o = 4; o >= 1; o >>= 1) den += __shfl_xor_sync(0xffffffffu, den, o);
        float inv = 1.f / den;
        int trow = t0 + row;
        for (int i = l8; i < 128; i += 8) {
            float wv = (i < trow) ? __expf(ss[row * 128 + i] - m) * inv : 0.f;
            ss[row * 128 + i] = wv;
        }
    }
    __syncthreads();

    int d0 = tx << 1;
    float2 accv[16];
#pragma unroll
    for (int q = 0; q < 16; q++) { accv[q].x = 0.f; accv[q].y = 0.f; }
    for (int s = 0; s < SEQ; s++) {
        const float* orow = g_out + (size_t)(b * SEQ + s) * HID;
        float2 v = *(const float2*)(orow + d0);
#pragma unroll
        for (int q = 0; q < 16; q++) {
            float wv = ss[q * 128 + s];
            accv[q].x += wv * v.x;
            accv[q].y += wv * v.y;
        }
    }
#pragma unroll
    for (int q = 0; q < 16; q++) {
        float* arow = g_attn + (size_t)(b * SEQ + t0 + q) * HID;
        *(float2*)(arow + d0) = accv[q];
    }
}

// ---------------- host launch ----------------
extern "C" void kernel_launch(void* const* d_in, const int* in_sizes, int n_in,
                              void* d_out, int out_size) {
    (void)in_sizes; (void)n_in; (void)out_size;
    const float* x      = (const float*)d_in[0];
    const int*   y      = (const int*)  d_in[1];
    const int*   lens   = (const int*)  d_in[2];
    const float* fc1_w  = (const float*)d_in[3];
    const float* fc1_b  = (const float*)d_in[4];
    const float* bn_g   = (const float*)d_in[5];
    const float* bn_b   = (const float*)d_in[6];
    const float* emb    = (const float*)d_in[7];
    const float* w_ih   = (const float*)d_in[8];
    const float* w_hh   = (const float*)d_in[9];
    const float* b_ih   = (const float*)d_in[10];
    const float* b_hh   = (const float*)d_in[11];
    const float* fc2_w  = (const float*)d_in[12];
    const float* fc2_b  = (const float*)d_in[13];
    float* out = (float*)d_out;

    cudaFuncSetAttribute(lstm_persist_kernel, cudaFuncAttributeMaxDynamicSharedMemorySize, LSTM_SMEM);
    cudaFuncSetAttribute(mma_gemm_kernel,     cudaFuncAttributeMaxDynamicSharedMemorySize, MMA_SMEM);

    float *p_seq, *p_xih, *p_attn;
    __nv_bfloat16 *p_Ah, *p_Al, *p_Wh, *p_Wl;
    cudaGetSymbolAddress((void**)&p_seq,  g_seq);
    cudaGetSymbolAddress((void**)&p_xih,  g_xih);
    cudaGetSymbolAddress((void**)&p_attn, g_attn);
    cudaGetSymbolAddress((void**)&p_Ah, g_Ah);
    cudaGetSymbolAddress((void**)&p_Al, g_Al);
    cudaGetSymbolAddress((void**)&p_Wh, g_Wh);
    cudaGetSymbolAddress((void**)&p_Wl, g_Wl);

    init_hc_kernel<<<(BB * HID + 255) / 256, 256>>>();
    fc1_kernel<<<(BB * EMB) / 256, 256>>>(x, fc1_w, fc1_b);
    bn_kernel<<<EMB, 64>>>(bn_g, bn_b);
    embed_kernel<<<(BB * TT * (EMB / 4)) / 256, 256>>>(y, emb);

    const int Mrows = BB * SEQ;                   // 8192

    // ---- X_ih = seq @ W_ih^T + (b_ih + b_hh) via split-bf16 warp MMA ----
    split_bf16_kernel<<<(Mrows * KDIM / 2 + 255) / 256, 256>>>(p_seq, p_Ah, p_Al, Mrows, Mrows);
    split_bf16_kernel<<<(G4 * KDIM / 2 + 255) / 256, 256>>>(w_ih, p_Wh, p_Wl, G4, G4);
    {
        dim3 g(G4 / 256, Mrows / 128);            // (8, 64)
        mma_gemm_kernel<<<g, 256, MMA_SMEM>>>(p_Ah, p_Al, p_Wh, p_Wl, b_ih, b_hh, p_xih, G4);
    }

    // ---- all 128 LSTM steps in ONE persistent kernel ----
    lstm_persist_kernel<<<128, 256, LSTM_SMEM>>>(w_hh, lens, p_xih);

    attn_kernel<<<dim3(SEQ / 16, BB), 256>>>();

    // ---- predictions = attn @ fc2_w^T + fc2_b via split-bf16 warp MMA ----
    split_bf16_kernel<<<(Mrows * KDIM / 2 + 255) / 256, 256>>>(p_attn, p_Ah, p_Al, Mrows, Mrows);
    split_bf16_kernel<<<(VOCP * KDIM / 2 + 255) / 256, 256>>>(fc2_w, p_Wh, p_Wl, VOC, VOCP);
    {
        dim3 g(VOCP / 256, Mrows / 128);          // (40, 64)
        mma_gemm_kernel<<<g, 256, MMA_SMEM>>>(p_Ah, p_Al, p_Wh, p_Wl, fc2_b, nullptr, out, VOC);
    }
}